// round 1
// baseline (speedup 1.0000x reference)
#include <cuda_runtime.h>

#define B_DIM   1024
#define C_DIM   64
#define W_DIM   40
#define NCLS    512
#define P_DIM   20480   // NCLS * W_DIM

// Scratch (device globals; no allocation allowed)
__device__ float g_xn[B_DIM * C_DIM * W_DIM];   // normalized conv, layout [b][c][w]
__device__ float g_pn[NCLS * C_DIM * W_DIM];    // normalized prototypes, layout [k][c][i]
__device__ float g_scls[B_DIM * NCLS];          // per-class sim sums

// ---------------------------------------------------------------------------
// K1: L2-normalize conv_features over C for each (b, w). Layout preserved.
// ---------------------------------------------------------------------------
__global__ void k_norm_x(const float* __restrict__ conv) {
    __shared__ float sx[C_DIM * W_DIM];   // [c][w]
    __shared__ float sinv[W_DIM];
    const int b = blockIdx.x;
    const int t = threadIdx.x;
    const float* src = conv + b * (C_DIM * W_DIM);
    for (int j = t; j < C_DIM * W_DIM; j += 256) sx[j] = src[j];
    __syncthreads();
    if (t < W_DIM) {
        float ss = 0.f;
        #pragma unroll
        for (int c = 0; c < C_DIM; c++) { float v = sx[c * W_DIM + t]; ss += v * v; }
        sinv[t] = 1.f / fmaxf(sqrtf(ss), 1e-12f);
    }
    __syncthreads();
    float* dst = g_xn + b * (C_DIM * W_DIM);
    for (int j = t; j < C_DIM * W_DIM; j += 256) dst[j] = sx[j] * sinv[j % W_DIM];
}

// ---------------------------------------------------------------------------
// K2: L2-normalize prototypes over C and transpose to [k][c][i], i = p % 40.
// Block k reads prototype rows p = k*40 .. k*40+39 (fully contiguous).
// ---------------------------------------------------------------------------
__global__ void k_norm_p(const float* __restrict__ proto) {
    __shared__ float sp[W_DIM * 66];      // [i][c], padded rows (bank relief)
    __shared__ float sinv[W_DIM];
    const int k = blockIdx.x;
    const int t = threadIdx.x;
    const float* src = proto + k * (W_DIM * C_DIM);
    for (int m = t; m < W_DIM * C_DIM; m += 256)
        sp[(m >> 6) * 66 + (m & 63)] = src[m];
    __syncthreads();
    if (t < W_DIM) {
        float ss = 0.f;
        #pragma unroll
        for (int c = 0; c < C_DIM; c++) { float v = sp[t * 66 + c]; ss += v * v; }
        sinv[t] = 1.f / fmaxf(sqrtf(ss), 1e-12f);
    }
    __syncthreads();
    float* dst = g_pn + k * (C_DIM * W_DIM);   // [c][i]
    for (int j = t; j < C_DIM * W_DIM; j += 256) {
        int c = j / W_DIM;
        int i = j - c * W_DIM;
        dst[j] = sp[i * 66 + c] * sinv[i];
    }
}

// ---------------------------------------------------------------------------
// K3: sim[b][k][i] = sum_c xn[b][c][i] * pn[k][c][i]
// Block tile: 32 b x 16 k x all 40 i.  320 threads = (tb 8) x (tk 4) x (ti 10).
// Thread microtile: 4b x 4k x 4i, fp32x2 packed FMA accumulators.
// Writes min_distances = -sim (streaming stores), and per-block class partial
// sums S_cls[b][k] (each (b,k) owned by exactly one block -> plain stores).
// ---------------------------------------------------------------------------
#define BT 32
#define KT 16
#define CCH 4

__global__ __launch_bounds__(320, 2) void k_gemm(float* __restrict__ md) {
    __shared__ float Xs[CCH * BT * W_DIM];   // [cc][bb][i]  5120 floats
    __shared__ float Ps[CCH * KT * W_DIM];   // [cc][kk][i]  2560 floats

    const int t  = threadIdx.x;
    const int ti = t % 10;
    const int tk = (t / 10) % 4;
    const int tb = t / 40;                // 0..7
    const int b0 = blockIdx.x * BT;
    const int k0 = blockIdx.y * KT;
    const int i4 = ti * 4;

    unsigned long long acc[4][4][2];
    #pragma unroll
    for (int rb = 0; rb < 4; rb++)
        #pragma unroll
        for (int rk = 0; rk < 4; rk++) { acc[rb][rk][0] = 0ull; acc[rb][rk][1] = 0ull; }

    for (int c0 = 0; c0 < C_DIM; c0 += CCH) {
        // cooperative copy: X tile (1280 float4) and P tile (640 float4)
        for (int m = t; m < CCH * BT * 10; m += 320) {
            int cc = m / (BT * 10);
            int r  = m - cc * (BT * 10);
            int bb = r / 10;
            int iq = r - bb * 10;
            reinterpret_cast<float4*>(Xs)[m] =
                *reinterpret_cast<const float4*>(&g_xn[(b0 + bb) * (C_DIM * W_DIM) + (c0 + cc) * W_DIM + iq * 4]);
        }
        for (int m = t; m < CCH * KT * 10; m += 320) {
            int cc = m / (KT * 10);
            int r  = m - cc * (KT * 10);
            int kk = r / 10;
            int iq = r - kk * 10;
            reinterpret_cast<float4*>(Ps)[m] =
                *reinterpret_cast<const float4*>(&g_pn[(k0 + kk) * (C_DIM * W_DIM) + (c0 + cc) * W_DIM + iq * 4]);
        }
        __syncthreads();

        #pragma unroll
        for (int cc = 0; cc < CCH; cc++) {
            unsigned long long xf[4][2], pf[4][2];
            #pragma unroll
            for (int rb = 0; rb < 4; rb++) {
                ulonglong2 v = *reinterpret_cast<const ulonglong2*>(
                    &Xs[(cc * BT + tb * 4 + rb) * W_DIM + i4]);
                xf[rb][0] = v.x; xf[rb][1] = v.y;
            }
            #pragma unroll
            for (int rk = 0; rk < 4; rk++) {
                ulonglong2 v = *reinterpret_cast<const ulonglong2*>(
                    &Ps[(cc * KT + tk * 4 + rk) * W_DIM + i4]);
                pf[rk][0] = v.x; pf[rk][1] = v.y;
            }
            #pragma unroll
            for (int rb = 0; rb < 4; rb++)
                #pragma unroll
                for (int rk = 0; rk < 4; rk++) {
                    asm("fma.rn.f32x2 %0, %1, %2, %0;"
                        : "+l"(acc[rb][rk][0]) : "l"(xf[rb][0]), "l"(pf[rk][0]));
                    asm("fma.rn.f32x2 %0, %1, %2, %0;"
                        : "+l"(acc[rb][rk][1]) : "l"(xf[rb][1]), "l"(pf[rk][1]));
                }
        }
        __syncthreads();
    }

    // Epilogue: write -sim (streaming), collect class partials
    float part[4][4];
    #pragma unroll
    for (int rb = 0; rb < 4; rb++) {
        int b = b0 + tb * 4 + rb;
        #pragma unroll
        for (int rk = 0; rk < 4; rk++) {
            int k = k0 + tk * 4 + rk;
            float f0 = __uint_as_float((unsigned)(acc[rb][rk][0]));
            float f1 = __uint_as_float((unsigned)(acc[rb][rk][0] >> 32));
            float f2 = __uint_as_float((unsigned)(acc[rb][rk][1]));
            float f3 = __uint_as_float((unsigned)(acc[rb][rk][1] >> 32));
            float4 o = make_float4(-f0, -f1, -f2, -f3);
            __stcs(reinterpret_cast<float4*>(&md[(size_t)b * P_DIM + k * W_DIM + i4]), o);
            part[rb][rk] = f0 + f1 + f2 + f3;
        }
    }

    // Reduce partials over the 10 ti-threads sharing each (b,k). Reuse Xs.
    __syncthreads();
    #pragma unroll
    for (int rb = 0; rb < 4; rb++)
        #pragma unroll
        for (int rk = 0; rk < 4; rk++)
            Xs[ti * 512 + (tb * 4 + rb) * KT + tk * 4 + rk] = part[rb][rk];
    __syncthreads();
    for (int bk = t; bk < BT * KT; bk += 320) {
        float s = 0.f;
        #pragma unroll
        for (int q = 0; q < 10; q++) s += Xs[q * 512 + bk];
        g_scls[(b0 + (bk >> 4)) * NCLS + k0 + (bk & 15)] = s;
    }
}

// ---------------------------------------------------------------------------
// K4: logits[b][cls] = 1.5*S_cls - 0.5*S_total
// ---------------------------------------------------------------------------
__global__ void k_logits(float* __restrict__ out) {
    __shared__ float red[512];
    const int b = blockIdx.x;
    const int t = threadIdx.x;
    float s = g_scls[b * NCLS + t];
    red[t] = s;
    __syncthreads();
    for (int off = 256; off > 0; off >>= 1) {
        if (t < off) red[t] += red[t + off];
        __syncthreads();
    }
    float tot = red[0];
    out[b * NCLS + t] = 1.5f * s - 0.5f * tot;
}

// ---------------------------------------------------------------------------
extern "C" void kernel_launch(void* const* d_in, const int* in_sizes, int n_in,
                              void* d_out, int out_size) {
    const float* conv  = (const float*)d_in[0];   // (1024, 64, 1, 40)
    const float* proto = (const float*)d_in[1];   // (20480, 64, 1, 1)
    // d_in[2] (last_layer_weight) and d_in[3] (offset_tensor) are analytic — unused.

    float* out    = (float*)d_out;
    float* logits = out;                                // (1024, 512)
    float* md     = out + (size_t)B_DIM * NCLS;         // (1024, 20480)

    k_norm_x<<<B_DIM, 256>>>(conv);
    k_norm_p<<<NCLS, 256>>>(proto);
    k_gemm<<<dim3(B_DIM / BT, NCLS / KT), 320>>>(md);
    k_logits<<<B_DIM, 512>>>(logits);
}